// round 10
// baseline (speedup 1.0000x reference)
#include <cuda_runtime.h>

#define BSZ 32
#define DIM 5120
#define NH 64
#define NKV 8
#define HD 128
#define HID 25600
#define SEQL 1024
#define SLOTS 296
#define SLOT_ELEMS (32 * 512)

typedef unsigned long long ull;

// ---------------- scratch (device globals; no allocation allowed) ----------------
__device__ float g_an[BSZ * DIM];
__device__ float g_q[BSZ * NH * HD];
__device__ float g_k[BSZ * NKV * HD];
__device__ float g_attn[BSZ * NH * HD];
__device__ float g_h[BSZ * DIM];
__device__ float g_fn[BSZ * DIM];
__device__ float g_hidden[BSZ * HID];
__device__ float g_part[SLOTS * SLOT_ELEMS];    // wq, wo, w1, w2 partials (18.6MB)
__device__ float g_part2[SLOTS * SLOT_ELEMS];   // wk, wv, w3 partials

__device__ __forceinline__ int slot_base(int nb, int q, int r) {
    return nb < r ? nb * (q + 1) : r * (q + 1) + (nb - r) * q;
}

__device__ __forceinline__ void cpasync16(unsigned smem_addr, const void* gptr) {
    asm volatile("cp.async.cg.shared.global [%0], [%1], 16;" :: "r"(smem_addr), "l"(gptr));
}

__device__ __forceinline__ unsigned cvt_tf32(float f) {
    unsigned r;
    asm("cvt.rna.tf32.f32 %0, %1;" : "=r"(r) : "f"(f));
    return r;
}

// ---------------- helpers ----------------
__device__ __forceinline__ float block_sum_256(float v) {
    #pragma unroll
    for (int off = 16; off; off >>= 1) v += __shfl_xor_sync(0xffffffffu, v, off);
    __shared__ float red[8];
    __shared__ float total;
    int w = threadIdx.x >> 5, lane = threadIdx.x & 31;
    if (lane == 0) red[w] = v;
    __syncthreads();
    if (threadIdx.x < 32) {
        float t = (threadIdx.x < 8) ? red[threadIdx.x] : 0.f;
        #pragma unroll
        for (int off = 4; off; off >>= 1) t += __shfl_xor_sync(0xffffffffu, t, off);
        if (threadIdx.x == 0) total = t;
    }
    __syncthreads();
    return total;
}

// ---------------- rmsnorm of x -> g_an ----------------
__global__ void rmsnorm_kernel(const float* __restrict__ x, const float* __restrict__ w) {
    int b = blockIdx.x, tid = threadIdx.x;     // 256 threads
    const float* xr = x + (size_t)b * DIM;
    float v[20];
    float ss = 0.f;
    #pragma unroll
    for (int i = 0; i < 20; i++) { v[i] = xr[tid + 256 * i]; ss += v[i] * v[i]; }
    ss = block_sum_256(ss);
    float rs = rsqrtf(ss / (float)DIM + 1e-5f);
    #pragma unroll
    for (int i = 0; i < 20; i++) {
        int n = tid + 256 * i;
        g_an[(size_t)b * DIM + n] = v[i] * rs * w[n];
    }
}

// ---------------- GEMM v5 (tf32 mma.sync): C[32][N] = A[32][K]*W[N][K]^T ----
// Tile 512 cols x KC=16. cp.async double-buffered W, swizzle s(n)=(n>>1)&3, pitch 16.
// 8 warps; warp w = cols [64w,64w+64) (8 n8-tiles) x 32 m (2 m16-tiles). acc 64/thread.
__global__ void __launch_bounds__(256, 2)
gemm5(const float* __restrict__ A, const float* __restrict__ W, float* __restrict__ P,
      int N, int K, int q, int r, int sbase) {
    extern __shared__ float smem[];
    const int WSO[2] = {0, 8192};
    const int ASO[2] = {16384, 16384 + 576};

    unsigned smem_base;
    asm("{.reg .u64 t; cvta.to.shared.u64 t, %1; cvt.u32.u64 %0, t;}"
        : "=r"(smem_base) : "l"(smem));

    int b = blockIdx.x;
    int qp1 = q + 1;
    int nb, s, KS;
    if (b < r * qp1) { nb = b / qp1; s = b - nb * qp1; KS = qp1; }
    else { int b2 = b - r * qp1; nb = r + b2 / q; s = b2 - (nb - r) * q; KS = q; }
    int Klen = ((K + KS * 16 - 1) / (KS * 16)) * 16;
    int kb = s * Klen;
    int ke = min(kb + Klen, K);
    int nbase = nb * 512;
    int nchunks = (ke > kb) ? (ke - kb) / 16 : 0;

    int tid = threadIdx.x;
    int warp = tid >> 5, lane = tid & 31;
    int g = lane >> 2, u = lane & 3;
    int wn0 = warp * 64;

    float acc[2][8][4];
    #pragma unroll
    for (int mt = 0; mt < 2; mt++)
        #pragma unroll
        for (int nt = 0; nt < 8; nt++)
            #pragma unroll
            for (int cc = 0; cc < 4; cc++) acc[mt][nt][cc] = 0.f;

    int am = tid >> 2, akq = tid & 3;   // A staging (tid<128): row, k-quad
    float4 areg = make_float4(0.f, 0.f, 0.f, 0.f);

    if (nchunks > 0) {
        #pragma unroll
        for (int j = 0; j < 8; j++) {
            int idx = j * 256 + tid;
            int kq = idx >> 9, n = idx & 511;
            unsigned dst = smem_base + (unsigned)((WSO[0] + n * 16 + 4 * (kq ^ ((n >> 1) & 3))) * 4);
            cpasync16(dst, W + (size_t)(nbase + n) * K + kb + 4 * kq);
        }
        asm volatile("cp.async.commit_group;" ::: "memory");
        if (tid < 128)
            areg = *reinterpret_cast<const float4*>(A + (size_t)am * K + kb + 4 * akq);
    }

    for (int i = 0; i < nchunks; i++) {
        int cur = i & 1;
        if (tid < 128) {
            float* p = smem + ASO[cur] + (4 * akq) * 36 + am;
            p[0] = areg.x; p[36] = areg.y; p[72] = areg.z; p[108] = areg.w;
        }
        bool hasnext = (i + 1 < nchunks);
        if (hasnext) {
            int kn = kb + (i + 1) * 16;
            int nxt = 1 - cur;
            #pragma unroll
            for (int j = 0; j < 8; j++) {
                int idx = j * 256 + tid;
                int kq = idx >> 9, n = idx & 511;
                unsigned dst = smem_base + (unsigned)((WSO[nxt] + n * 16 + 4 * (kq ^ ((n >> 1) & 3))) * 4);
                cpasync16(dst, W + (size_t)(nbase + n) * K + kn + 4 * kq);
            }
            asm volatile("cp.async.commit_group;" ::: "memory");
            if (tid < 128)
                areg = *reinterpret_cast<const float4*>(A + (size_t)am * K + kn + 4 * akq);
            asm volatile("cp.async.wait_group 1;" ::: "memory");
        } else {
            asm volatile("cp.async.wait_group 0;" ::: "memory");
        }
        __syncthreads();

        const float* ws = smem + WSO[cur];
        const float* as = smem + ASO[cur];
        #pragma unroll
        for (int k8 = 0; k8 < 16; k8 += 8) {
            unsigned afr[2][4];
            #pragma unroll
            for (int mt = 0; mt < 2; mt++) {
                int m = mt * 16 + g;
                afr[mt][0] = cvt_tf32(as[(k8 + u) * 36 + m]);
                afr[mt][1] = cvt_tf32(as[(k8 + u) * 36 + m + 8]);
                afr[mt][2] = cvt_tf32(as[(k8 + u + 4) * 36 + m]);
                afr[mt][3] = cvt_tf32(as[(k8 + u + 4) * 36 + m + 8]);
            }
            int q0 = k8 >> 2, q1 = q0 + 1;
            #pragma unroll
            for (int nt = 0; nt < 8; nt++) {
                int n = wn0 + nt * 8 + g;
                int sw = (n >> 1) & 3;
                unsigned b0 = cvt_tf32(ws[n * 16 + 4 * (q0 ^ sw) + u]);
                unsigned b1 = cvt_tf32(ws[n * 16 + 4 * (q1 ^ sw) + u]);
                #pragma unroll
                for (int mt = 0; mt < 2; mt++) {
                    asm("mma.sync.aligned.m16n8k8.row.col.f32.tf32.tf32.f32 "
                        "{%0,%1,%2,%3}, {%4,%5,%6,%7}, {%8,%9}, {%0,%1,%2,%3};"
                        : "+f"(acc[mt][nt][0]), "+f"(acc[mt][nt][1]),
                          "+f"(acc[mt][nt][2]), "+f"(acc[mt][nt][3])
                        : "r"(afr[mt][0]), "r"(afr[mt][1]), "r"(afr[mt][2]), "r"(afr[mt][3]),
                          "r"(b0), "r"(b1));
                }
            }
        }
        __syncthreads();
    }

    float* po = P + (size_t)(sbase + b) * SLOT_ELEMS;
    #pragma unroll
    for (int mt = 0; mt < 2; mt++) {
        #pragma unroll
        for (int nt = 0; nt < 8; nt++) {
            int col = wn0 + nt * 8 + 2 * u;
            int r0 = mt * 16 + g;
            *reinterpret_cast<float2*>(po + r0 * 512 + col) =
                make_float2(acc[mt][nt][0], acc[mt][nt][1]);
            *reinterpret_cast<float2*>(po + (r0 + 8) * 512 + col) =
                make_float2(acc[mt][nt][2], acc[mt][nt][3]);
        }
    }
}

// ---------------- split-K sum helper (512-col slots, deterministic order) --------
__device__ __forceinline__ float4 sum_slots(const float* __restrict__ P,
                                            int m, int n, int q, int r, int sbase) {
    int nb = n >> 9, cl = n & 511;
    int sb = sbase + slot_base(nb, q, r);
    int cnt = nb < r ? q + 1 : q;
    const float* base = P + (size_t)sb * SLOT_ELEMS + m * 512 + cl;
    float4 s = make_float4(0.f, 0.f, 0.f, 0.f);
    for (int k = 0; k < cnt; k++) {
        float4 t = *reinterpret_cast<const float4*>(base + (size_t)k * SLOT_ELEMS);
        s.x += t.x; s.y += t.y; s.z += t.z; s.w += t.w;
    }
    return s;
}

__device__ __forceinline__ float silu_f(float x) { return x / (1.f + __expf(-x)); }

// hidden = silu(sum w1 partials) * (sum w3 partials)
__global__ void reduce_silu2(int N, int q, int r) {
    int i = blockIdx.x * blockDim.x + threadIdx.x;
    int n4 = N >> 2;
    if (i >= 32 * n4) return;
    int m = i / n4, n = (i - m * n4) * 4;
    float4 s1 = sum_slots(g_part, m, n, q, r, 0);
    float4 s3 = sum_slots(g_part2, m, n, q, r, 0);
    float4 o;
    o.x = silu_f(s1.x) * s3.x; o.y = silu_f(s1.y) * s3.y;
    o.z = silu_f(s1.z) * s3.z; o.w = silu_f(s1.w) * s3.w;
    *reinterpret_cast<float4*>(g_hidden + (size_t)m * N + n) = o;
}

// out = h + sum of w2 partials
__global__ void final_kernel(float* __restrict__ out, int N, int q, int r) {
    int i = blockIdx.x * blockDim.x + threadIdx.x;
    int n4 = N >> 2;
    if (i >= 32 * n4) return;
    int m = i / n4, n = (i - m * n4) * 4;
    float4 s = sum_slots(g_part, m, n, q, r, 0);
    float4 h = *reinterpret_cast<const float4*>(g_h + (size_t)m * N + n);
    s.x += h.x; s.y += h.y; s.z += h.z; s.w += h.w;
    *reinterpret_cast<float4*>(out + (size_t)m * N + n) = s;
}

// ---------------- fused q/k reduce + per-head rmsnorm (eps 1e-6) + RoPE ----------
__global__ void qknorm_rope2(const float* __restrict__ fc, const float* __restrict__ fs,
                             const float* __restrict__ qw, const float* __restrict__ kw) {
    int id = blockIdx.x, tid = threadIdx.x;   // 128 threads
    float v = 0.f;
    const float* w;
    float* outp;
    if (id < BSZ * NH) {
        int b = id >> 6, hd = id & 63;
        int n = hd * 128 + tid;
        int nb = n >> 9, cl = n & 511;
        int sb = slot_base(nb, 18, 8);
        int cnt = nb < 8 ? 19 : 18;
        const float* base = g_part + (size_t)sb * SLOT_ELEMS + b * 512 + cl;
        for (int k = 0; k < cnt; k++) v += base[(size_t)k * SLOT_ELEMS];
        w = qw; outp = g_q + (size_t)id * HD;
    } else {
        int kid = id - BSZ * NH;
        int b = kid >> 3, gg = kid & 7;
        int n = gg * 128 + tid;
        int nb = n >> 9, cl = n & 511;
        const float* base = g_part2 + (size_t)(nb * 32) * SLOT_ELEMS + b * 512 + cl;
        for (int k = 0; k < 32; k++) v += base[(size_t)k * SLOT_ELEMS];
        w = kw; outp = g_k + (size_t)kid * HD;
    }
    float ss = v * v;
    #pragma unroll
    for (int off = 16; off; off >>= 1) ss += __shfl_xor_sync(0xffffffffu, ss, off);
    __shared__ float red[4];
    __shared__ float s_rs;
    __shared__ float nbuf[HD];
    int wp = tid >> 5, lane = tid & 31;
    if (lane == 0) red[wp] = ss;
    __syncthreads();
    if (tid == 0) s_rs = rsqrtf((red[0] + red[1] + red[2] + red[3]) / (float)HD + 1e-6f);
    __syncthreads();
    float nv = v * s_rs * w[tid];
    nbuf[tid] = nv;
    __syncthreads();
    int i = tid >> 1;
    float c = fc[i], s = fs[i];
    float ne = nbuf[tid & ~1], no = nbuf[tid | 1];
    float o = (tid & 1) ? (ne * s + no * c) : (ne * c - no * s);
    outp[tid] = o;
}

// ---------------- attention: fused v reduce; 512 threads; PV split over 2 warps/head ----
__global__ void __launch_bounds__(512, 1)
attn2(const float* __restrict__ ck, const float* __restrict__ cv) {
    __shared__ float sc[NKV][SEQL];     // 32 KB
    __shared__ float vlast[HD];
    __shared__ float pvp[8][2][HD];     // 8 KB
    __shared__ float sinv[8];
    int bg = blockIdx.x;
    int b = bg >> 3, g = bg & 7;
    int tid = threadIdx.x, warp = tid >> 5, lane = tid & 31;
    const float scale = 0.08838834764831845f;   // 1/sqrt(128)

    // fused v reduce: last-position v for this (b, g)
    if (tid < HD) {
        int n = g * HD + tid;
        int nb = n >> 9, cl = n & 511;
        const float* base = g_part2 + (size_t)(64 + nb * 32) * SLOT_ELEMS + b * 512 + cl;
        float s = 0.f;
        for (int k = 0; k < 32; k++) s += base[(size_t)k * SLOT_ELEMS];
        vlast[tid] = s;
    }

    float4 qreg[8];
    #pragma unroll
    for (int h = 0; h < 8; h++) {
        float4 t = *reinterpret_cast<const float4*>(
            g_q + ((size_t)(b * NH + g * 8 + h)) * HD + lane * 4);
        qreg[h] = make_float4(t.x * scale, t.y * scale, t.z * scale, t.w * scale);
    }

    // scores: 16 warps stride over key positions
    for (int l = warp; l < SEQL; l += 16) {
        const float* kp = (l < SEQL - 1)
            ? (ck + ((size_t)(b * SEQL + l) * NKV + g) * HD)
            : (g_k + (size_t)(b * NKV + g) * HD);
        float4 k4 = *reinterpret_cast<const float4*>(kp + lane * 4);
        float s[8];
        #pragma unroll
        for (int h = 0; h < 8; h++)
            s[h] = qreg[h].x * k4.x + qreg[h].y * k4.y + qreg[h].z * k4.z + qreg[h].w * k4.w;
        #pragma unroll
        for (int h = 0; h < 8; h++) {
            #pragma unroll
            for (int off = 16; off; off >>= 1)
                s[h] += __shfl_xor_sync(0xffffffffu, s[h], off);
        }
        float myv = s[0];
        #pragma unroll
        for (int h = 1; h < 8; h++) if (lane == h) myv = s[h];
        if (lane < 8) sc[lane][l] = myv;
    }
    __syncthreads();

    // softmax: warp per head (warps 0-7)
    if (warp < 8) {
        int h = warp;
        float mx = -1e30f;
        for (int l = lane; l < SEQL; l += 32) mx = fmaxf(mx, sc[h][l]);
        #pragma unroll
        for (int off = 16; off; off >>= 1)
            mx = fmaxf(mx, __shfl_xor_sync(0xffffffffu, mx, off));
        float sum = 0.f;
        for (int l = lane; l < SEQL; l += 32) {
            float e = __expf(sc[h][l] - mx);
            sc[h][l] = e;
            sum += e;
        }
        #pragma unroll
        for (int off = 16; off; off >>= 1) sum += __shfl_xor_sync(0xffffffffu, sum, off);
        if (lane == 0) sinv[h] = 1.f / sum;
    }
    __syncthreads();

    // PV: warp = (head, half); each covers 512 positions, 4 independent accumulators
    {
        int h = warp >> 1, half = warp & 1;
        float4 a0 = make_float4(0,0,0,0), a1 = a0, a2 = a0, a3 = a0;
        int l0 = half * 512;
        for (int l = l0; l < l0 + 512; l += 4) {
            #pragma unroll
            for (int j = 0; j < 4; j++) {
                int lj = l + j;
                float p = sc[h][lj];
                float4 v4 = (lj < SEQL - 1)
                    ? *reinterpret_cast<const float4*>(cv + ((size_t)(b * SEQL + lj) * NKV + g) * HD + lane * 4)
                    : *reinterpret_cast<const float4*>(vlast + lane * 4);
                float4& a = (j == 0) ? a0 : (j == 1) ? a1 : (j == 2) ? a2 : a3;
                a.x += p * v4.x; a.y += p * v4.y; a.z += p * v4.z; a.w += p * v4.w;
            }
        }
        float4 acc;
        acc.x = (a0.x + a1.x) + (a2.x + a3.x);
        acc.y = (a0.y + a1.y) + (a2.y + a3.y);
        acc.z = (a0.z + a1.z) + (a2.z + a3.z);
        acc.w = (a0.w + a1.w) + (a2.w + a3.w);
        *reinterpret_cast<float4*>(&pvp[h][half][lane * 4]) = acc;
    }
    __syncthreads();

    // combine halves + scale (warps 0-7)
    if (warp < 8) {
        int h = warp;
        float4 A0 = *reinterpret_cast<const float4*>(&pvp[h][0][lane * 4]);
        float4 A1 = *reinterpret_cast<const float4*>(&pvp[h][1][lane * 4]);
        float inv = sinv[h];
        *reinterpret_cast<float4*>(g_attn + ((size_t)(b * NH + g * 8 + h)) * HD + lane * 4) =
            make_float4((A0.x + A1.x) * inv, (A0.y + A1.y) * inv,
                        (A0.z + A1.z) * inv, (A0.w + A1.w) * inv);
    }
}

// ---------------- h = x + wo partials; fn = rmsnorm(h) ----------------
__global__ void hnorm_kernel(const float* __restrict__ x, const float* __restrict__ w,
                             int q, int r) {
    int b = blockIdx.x, tid = threadIdx.x;  // 256 threads
    float hv[20];
    float ss = 0.f;
    #pragma unroll
    for (int i = 0; i < 20; i++) {
        int n = tid + 256 * i;
        int nb = n >> 9, cl = n & 511;
        int sb = slot_base(nb, q, r);
        int cnt = nb < r ? q + 1 : q;
        float s = x[(size_t)b * DIM + n];
        const float* base = g_part + (size_t)sb * SLOT_ELEMS + b * 512 + cl;
        for (int k = 0; k < cnt; k++)
            s += base[(size_t)k * SLOT_ELEMS];
        hv[i] = s;
        g_h[(size_t)b * DIM + n] = s;
        ss += s * s;
    }
    ss = block_sum_256(ss);
    float rs = rsqrtf(ss / (float)DIM + 1e-5f);
    #pragma unroll
    for (int i = 0; i < 20; i++) {
        int n = tid + 256 * i;
        g_fn[(size_t)b * DIM + n] = hv[i] * rs * w[n];
    }
}

// ---------------- host ----------------
extern "C" void kernel_launch(void* const* d_in, const int* in_sizes, int n_in,
                              void* d_out, int out_size) {
    (void)in_sizes; (void)n_in; (void)out_size;
    const float* x   = (const float*)d_in[0];
    const float* fc  = (const float*)d_in[2];
    const float* fs  = (const float*)d_in[3];
    const float* ck  = (const float*)d_in[5];
    const float* cv  = (const float*)d_in[6];
    const float* wq  = (const float*)d_in[7];
    const float* wk  = (const float*)d_in[8];
    const float* wv  = (const float*)d_in[9];
    const float* wo  = (const float*)d_in[10];
    const float* w1  = (const float*)d_in[11];
    const float* w2  = (const float*)d_in[12];
    const float* w3  = (const float*)d_in[13];
    const float* anw = (const float*)d_in[14];
    const float* fnw = (const float*)d_in[15];
    const float* qnw = (const float*)d_in[16];
    const float* knw = (const float*)d_in[17];

    float *p_an, *p_attn, *p_fn, *p_hidden, *p_part, *p_part2;
    cudaGetSymbolAddress((void**)&p_an, g_an);
    cudaGetSymbolAddress((void**)&p_attn, g_attn);
    cudaGetSymbolAddress((void**)&p_fn, g_fn);
    cudaGetSymbolAddress((void**)&p_hidden, g_hidden);
    cudaGetSymbolAddress((void**)&p_part, g_part);
    cudaGetSymbolAddress((void**)&p_part2, g_part2);

    const int SMB = (16384 + 2 * 576) * 4;   // 70144 bytes
    cudaFuncSetAttribute(gemm5, cudaFuncAttributeMaxDynamicSharedMemorySize, SMB);

    // slot maps (512-col n-blocks):
    // wq:  N=8192,  NB=16 -> q=18, r=8   (296 CTAs, g_part base 0)
    // wk:  N=1024,  NB=2  -> q=32, r=0   (64 CTAs,  g_part2 base 0)
    // wv:  N=1024,  NB=2  -> q=32, r=0   (64 CTAs,  g_part2 base 64)
    // wo/w2: N=5120, NB=10 -> q=29, r=6  (296 CTAs, g_part base 0)
    // w1/w3: N=25600, NB=50 -> q=5, r=46 (296 CTAs)

    rmsnorm_kernel<<<32, 256>>>(x, anw);                                      // 0
    gemm5<<<64, 256, SMB>>>(p_an, wk, p_part2, NKV * HD, DIM, 32, 0, 0);      // 1
    gemm5<<<64, 256, SMB>>>(p_an, wv, p_part2, NKV * HD, DIM, 32, 0, 64);     // 2
    gemm5<<<SLOTS, 256, SMB>>>(p_an, wq, p_part, NH * HD, DIM, 18, 8, 0);     // 3 <- ncu
    qknorm_rope2<<<BSZ * NH + BSZ * NKV, 128>>>(fc, fs, qnw, knw);            // 4
    attn2<<<BSZ * NKV, 512>>>(ck, cv);                                        // 5
    gemm5<<<SLOTS, 256, SMB>>>(p_attn, wo, p_part, DIM, NH * HD, 29, 6, 0);   // 6
    hnorm_kernel<<<32, 256>>>(x, fnw, 29, 6);                                 // 7
    gemm5<<<SLOTS, 256, SMB>>>(p_fn, w1, p_part, HID, DIM, 5, 46, 0);         // 8
    gemm5<<<SLOTS, 256, SMB>>>(p_fn, w3, p_part2, HID, DIM, 5, 46, 0);        // 9
    reduce_silu2<<<(BSZ * HID / 4 + 255) / 256, 256>>>(HID, 5, 46);           // 10
    gemm5<<<SLOTS, 256, SMB>>>(p_hidden, w2, p_part, DIM, HID, 29, 6, 0);     // 11
    final_kernel<<<(BSZ * DIM / 4 + 255) / 256, 256>>>((float*)d_out, DIM, 29, 6); // 12
}